// round 15
// baseline (speedup 1.0000x reference)
#include <cuda_runtime.h>
#include <cuda_fp16.h>

// B=512 rows, L=16 labels, N=8192 values. Single kernel, 1024 blocks.
// loss = sum_l inv[l] * A_l,  inv[l] = 1/((np*nn)^2 * 256)
// A_l  = sum_{i pos, j neg} S[i,j],  S[i,j] = sum_{c,d} relu(1 - x[i,c] + x[j,d])
// Warp-autonomous: each thread LDGs its own i-row/j-row (L1-broadcast), no
// smem tile staging, NO barrier before the hot loop. Hot loop: HFMA2.RELU +
// HADD2 (1 fma-pipe instr per element pair). Skeletal epilogue; per-label
// partials -> g_acc[16] in 2^26 fixed point; ticketed last block combines.

#define NROW 512
#define NL   16
#define TI   16
#define GB   32
#define NBLK 1024
#define FPSCALE    67108864.0f   // 2^26
#define FPSCALE_I  (1.0f / 67108864.0f)

__device__ float              g_inv[NL];
__device__ unsigned long long g_acc[NL];     // zero-initialized at load
__device__ unsigned int       g_cnt = 0;

__global__ void __launch_bounds__(256, 6) k_all(const int* __restrict__ yt,
                                                const float* __restrict__ yp,
                                                float* __restrict__ out, int n_out) {
    __shared__ float    Ss[256];        // per-thread S
    __shared__ float    A2[NL * 17];    // stage-2 partials [l][ic]
    __shared__ float    wfin[NL];
    __shared__ unsigned pmI[TI], nmJ[TI];
    __shared__ int      cnt_s[NL];
    __shared__ int      is_last;

    const int b   = blockIdx.x;
    const int bi  = b & (GB - 1);
    const int bj  = b >> 5;
    const int tid = threadIdx.x;
    const int il  = tid >> 4;
    const int jl  = tid & 15;

    // ---- issue own-row loads first (latency overlapped with mask work) -----------
    const float4* ip = (const float4*)(yp + bi * 256 + il * TI);
    const float4* jp = (const float4*)(yp + bj * 256 + jl * TI);
    float4 i0 = ip[0], i1 = ip[1], i2 = ip[2], i3 = ip[3];
    float4 j0 = jp[0], j1 = jp[1], j2 = jp[2], j3 = jp[3];

    // ---- row masks (32 threads; consumed only after the post-hot-loop barrier) ----
    if (tid < 2 * TI) {
        int row = (tid < TI) ? (bi * TI + tid) : (bj * TI + (tid - TI));
        unsigned m = 0;
        const int4* y4 = (const int4*)(yt + row * NL);
        #pragma unroll
        for (int q = 0; q < 4; q++) {
            int4 v = y4[q];
            if (v.x) m |= 1u << (4 * q + 0);
            if (v.y) m |= 1u << (4 * q + 1);
            if (v.z) m |= 1u << (4 * q + 2);
            if (v.w) m |= 1u << (4 * q + 3);
        }
        if (tid < TI) pmI[tid] = m;
        else          nmJ[tid - TI] = (~m) & 0xFFFFu;
    }

    // ---- block 0 only: per-label n_pos -> g_inv (block-uniform branch) ------------
    if (b == 0) {
        if (tid < NL) cnt_s[tid] = 0;
        __syncthreads();
        const int r0 = 2 * tid;
        unsigned m0 = 0, m1 = 0;
        const int4* y4 = (const int4*)(yt + r0 * NL);
        #pragma unroll
        for (int q = 0; q < 4; q++) {
            int4 v = y4[q];
            if (v.x) m0 |= 1u << (4 * q + 0);
            if (v.y) m0 |= 1u << (4 * q + 1);
            if (v.z) m0 |= 1u << (4 * q + 2);
            if (v.w) m0 |= 1u << (4 * q + 3);
        }
        #pragma unroll
        for (int q = 0; q < 4; q++) {
            int4 v = y4[4 + q];
            if (v.x) m1 |= 1u << (4 * q + 0);
            if (v.y) m1 |= 1u << (4 * q + 1);
            if (v.z) m1 |= 1u << (4 * q + 2);
            if (v.w) m1 |= 1u << (4 * q + 3);
        }
        #pragma unroll
        for (int l = 0; l < NL; l++) {
            unsigned b0 = __ballot_sync(0xffffffffu, (m0 >> l) & 1u);
            unsigned b1 = __ballot_sync(0xffffffffu, (m1 >> l) & 1u);
            if ((tid & 31) == 0) atomicAdd(&cnt_s[l], __popc(b0) + __popc(b1));
        }
        __syncthreads();
        if (tid < NL) {
            int np = cnt_s[tid], nn = NROW - np;
            float d = (float)np * (float)nn;            // <= 2^18, exact in fp32
            g_inv[tid] = (np > 0 && nn > 0) ? 1.0f / (d * d * 256.0f) : 0.0f;
            // published by the same threads' __threadfence in the epilogue
        }
    }

    // ---- convert to packed fp16 in registers ---------------------------------------
    __half2 ah[8];
    ah[0] = __floats2half2_rn(1.0f - i0.x, 1.0f - i0.y);
    ah[1] = __floats2half2_rn(1.0f - i0.z, 1.0f - i0.w);
    ah[2] = __floats2half2_rn(1.0f - i1.x, 1.0f - i1.y);
    ah[3] = __floats2half2_rn(1.0f - i1.z, 1.0f - i1.w);
    ah[4] = __floats2half2_rn(1.0f - i2.x, 1.0f - i2.y);
    ah[5] = __floats2half2_rn(1.0f - i2.z, 1.0f - i2.w);
    ah[6] = __floats2half2_rn(1.0f - i3.x, 1.0f - i3.y);
    ah[7] = __floats2half2_rn(1.0f - i3.z, 1.0f - i3.w);

    __half2 xq[16];
    xq[ 0] = __float2half2_rn(j0.x);  xq[ 1] = __float2half2_rn(j0.y);
    xq[ 2] = __float2half2_rn(j0.z);  xq[ 3] = __float2half2_rn(j0.w);
    xq[ 4] = __float2half2_rn(j1.x);  xq[ 5] = __float2half2_rn(j1.y);
    xq[ 6] = __float2half2_rn(j1.z);  xq[ 7] = __float2half2_rn(j1.w);
    xq[ 8] = __float2half2_rn(j2.x);  xq[ 9] = __float2half2_rn(j2.y);
    xq[10] = __float2half2_rn(j2.z);  xq[11] = __float2half2_rn(j2.w);
    xq[12] = __float2half2_rn(j3.x);  xq[13] = __float2half2_rn(j3.y);
    xq[14] = __float2half2_rn(j3.z);  xq[15] = __float2half2_rn(j3.w);

    const __half2 one2 = __float2half2_rn(1.0f);
    const __half2 hz   = __float2half2_rn(0.0f);
    __half2 acc[8];
    #pragma unroll
    for (int k = 0; k < 8; k++) acc[k] = hz;

    // ---- hot loop: 256 element pairs, 1 fma-pipe instr per pair ---------------------
    #pragma unroll
    for (int d = 0; d < 16; d++) {
        #pragma unroll
        for (int k = 0; k < 8; k++) {
            __half2 r = __hfma2_relu(ah[k], one2, xq[d]);   // relu(ah + xq)
            acc[k] = __hadd2(acc[k], r);
        }
    }

    // tree-reduce the 8 half2 accumulators (values ~330 << 65504: safe)
    acc[0] = __hadd2(acc[0], acc[1]);
    acc[2] = __hadd2(acc[2], acc[3]);
    acc[4] = __hadd2(acc[4], acc[5]);
    acc[6] = __hadd2(acc[6], acc[7]);
    acc[0] = __hadd2(acc[0], acc[2]);
    acc[4] = __hadd2(acc[4], acc[6]);
    acc[0] = __hadd2(acc[0], acc[4]);
    float2 fS = __half22float2(acc[0]);

    // ---- skeletal epilogue: store S once, reconstruct label sums from masks ---------
    Ss[tid] = fS.x + fS.y;
    __syncthreads();

    {
        const int l = tid & 15, ic = tid >> 4;
        float a = 0.0f;
        if ((pmI[ic] >> l) & 1u) {
            #pragma unroll
            for (int j = 0; j < TI; j++)
                a += ((nmJ[j] >> l) & 1u) ? Ss[ic * TI + j] : 0.0f;
        }
        A2[l * 17 + ic] = a;
    }
    __syncthreads();

    if (tid < NL) {
        float s = 0.0f;
        #pragma unroll
        for (int c = 0; c < 16; c++) s += A2[tid * 17 + c];
        // deterministic fixed-point accumulation (A_l >= 0 always)
        atomicAdd(&g_acc[tid], (unsigned long long)__float2ll_rn(s * FPSCALE));
        __threadfence();            // also publishes block 0's g_inv writes
    }
    __syncthreads();

    if (tid == 0) {
        unsigned t = atomicAdd(&g_cnt, 1u);
        is_last = (t == NBLK - 1);
    }
    __syncthreads();

    // ---- last block: tiny tail --------------------------------------------------------
    if (is_last) {
        __threadfence();
        if (tid < NL) {
            long long v = (long long)g_acc[tid];
            wfin[tid] = (float)v * FPSCALE_I * g_inv[tid];
            g_acc[tid] = 0ULL;      // reset for next graph replay
        }
        __syncthreads();
        if (tid == 0) {
            float loss = 0.0f;
            #pragma unroll
            for (int l2 = 0; l2 < NL; l2++) loss += wfin[l2];
            out[0] = loss;
            g_cnt  = 0;             // reset for next graph replay
        }
        for (int i = tid + 1; i < n_out; i += 256) out[i] = 0.0f;
    }
}

extern "C" void kernel_launch(void* const* d_in, const int* in_sizes, int n_in,
                              void* d_out, int out_size) {
    const int*   yt  = (const int*)d_in[0];    // y_true int32 [512*16]
    const float* yp  = (const float*)d_in[1];  // y_pred fp32  [512*16]
    float*       out = (float*)d_out;

    k_all<<<NBLK, 256>>>(yt, yp, out, out_size);
}

// round 16
// speedup vs baseline: 1.1597x; 1.1597x over previous
#include <cuda_runtime.h>
#include <cuda_fp16.h>

// B=512 rows, L=16 labels, N=8192 values. Single kernel, 1024 blocks.
// loss = sum_l inv[l] * A_l,  inv[l] = 1/((np*nn)^2 * 256)
// A_l  = sum_{i pos, j neg} S[i,j],  S[i,j] = sum_{c,d} relu(1 - x[i,c] + x[j,d])
// Hot loop: HFMA2.RELU + HADD2 (1 fma-pipe instr per element pair).
// g_inv computation distributed over blocks 0..15 (one label each, no straggler).
// Stage-2 label sums via half-warp shuffles (no smem round-trip, one barrier less).
// Per-label partials -> g_acc[16] in 2^26 fixed point (deterministic);
// ticketed last block combines.

#define NROW 512
#define NL   16
#define TI   16
#define GB   32
#define NBLK 1024
#define FPSCALE    67108864.0f   // 2^26
#define FPSCALE_I  (1.0f / 67108864.0f)

__device__ float              g_inv[NL];
__device__ unsigned long long g_acc[NL];     // zero-initialized at load
__device__ unsigned int       g_cnt = 0;

__global__ void __launch_bounds__(256, 6) k_all(const int* __restrict__ yt,
                                                const float* __restrict__ yp,
                                                float* __restrict__ out, int n_out) {
    __shared__ __align__(16) __half  xih[TI * TI];   // (1-x) halves [i-row][c]
    __shared__ __align__(16) __half2 xjh2[TI * TI];  // splatted j halves [j-row][d]
    __shared__ float    A2[NL * 17];                 // stage-2 partials [l][ic]
    __shared__ float    wfin[NL];
    __shared__ unsigned pmI[TI], nmJ[TI];
    __shared__ int      wcnt[8];                     // per-warp popcounts (blocks<16)
    __shared__ int      is_last;

    const int b   = blockIdx.x;
    const int bi  = b & (GB - 1);
    const int bj  = b >> 5;
    const int tid = threadIdx.x;

    // ---- stage tiles (converted once here; consumers read fp16 directly) ----------
    {
        int r = tid >> 4, c = tid & 15;
        xih[r * TI + c]  = __float2half(1.0f - yp[bi * 256 + tid]);
        xjh2[r * TI + c] = __float2half2_rn(yp[bj * 256 + r * TI + c]);
    }

    // ---- row masks: 16 i-rows + 16 j-rows ------------------------------------------
    if (tid < 2 * TI) {
        int row = (tid < TI) ? (bi * TI + tid) : (bj * TI + (tid - TI));
        unsigned m = 0;
        const int4* y4 = (const int4*)(yt + row * NL);
        #pragma unroll
        for (int q = 0; q < 4; q++) {
            int4 v = y4[q];
            if (v.x) m |= 1u << (4 * q + 0);
            if (v.y) m |= 1u << (4 * q + 1);
            if (v.z) m |= 1u << (4 * q + 2);
            if (v.w) m |= 1u << (4 * q + 3);
        }
        if (tid < TI) pmI[tid] = m;
        else          nmJ[tid - TI] = (~m) & 0xFFFFu;
    }

    // ---- distributed g_inv: block b (b<16) counts label b (no extra barriers) -------
    if (b < NL) {
        int v0 = yt[tid * NL + b]         ? 1 : 0;   // rows 0..255
        int v1 = yt[(tid + 256) * NL + b] ? 1 : 0;   // rows 256..511
        unsigned b0 = __ballot_sync(0xffffffffu, v0);
        unsigned b1 = __ballot_sync(0xffffffffu, v1);
        if ((tid & 31) == 0) wcnt[tid >> 5] = __popc(b0) + __popc(b1);
    }
    __syncthreads();                     // covers staging, masks, and wcnt

    if (b < NL && tid == 0) {
        int np = ((wcnt[0] + wcnt[1]) + (wcnt[2] + wcnt[3]))
               + ((wcnt[4] + wcnt[5]) + (wcnt[6] + wcnt[7]));
        int nn = NROW - np;
        float d = (float)np * (float)nn;             // <= 2^18, exact in fp32
        g_inv[b] = (np > 0 && nn > 0) ? 1.0f / (d * d * 256.0f) : 0.0f;
        // ordered before this thread's g_cnt ticket by the epilogue __threadfence
    }

    // ---- hot loop --------------------------------------------------------------------
    const int il = tid >> 4;
    const int jl = tid & 15;

    // ah: 8 half2 of (1-x), read as 2x LDS.128 (half-warp broadcast, conflict-free)
    __half2 ah[8];
    {
        uint4 a0 = *(const uint4*)(xih + il * TI);
        uint4 a1 = *(const uint4*)(xih + il * TI + 8);
        unsigned aw[8] = {a0.x, a0.y, a0.z, a0.w, a1.x, a1.y, a1.z, a1.w};
        #pragma unroll
        for (int k = 0; k < 8; k++) ah[k] = *reinterpret_cast<__half2*>(&aw[k]);
    }

    const __half2 one2 = __float2half2_rn(1.0f);
    const __half2 hz   = __float2half2_rn(0.0f);
    __half2 acc[8];
    #pragma unroll
    for (int k = 0; k < 8; k++) acc[k] = hz;

    const uint4* qp = (const uint4*)&xjh2[jl * TI];   // 16 splatted half2
    #pragma unroll
    for (int dc = 0; dc < 4; dc++) {
        uint4 qv = qp[dc];
        unsigned qw[4] = {qv.x, qv.y, qv.z, qv.w};
        #pragma unroll
        for (int di = 0; di < 4; di++) {
            __half2 xq = *reinterpret_cast<__half2*>(&qw[di]);
            #pragma unroll
            for (int k = 0; k < 8; k++) {
                __half2 r = __hfma2_relu(ah[k], one2, xq);   // relu(ah + xq)
                acc[k] = __hadd2(acc[k], r);
            }
        }
    }

    // tree-reduce the 8 half2 accumulators (values ~330 << 65504: safe)
    acc[0] = __hadd2(acc[0], acc[1]);
    acc[2] = __hadd2(acc[2], acc[3]);
    acc[4] = __hadd2(acc[4], acc[5]);
    acc[6] = __hadd2(acc[6], acc[7]);
    acc[0] = __hadd2(acc[0], acc[2]);
    acc[4] = __hadd2(acc[4], acc[6]);
    acc[0] = __hadd2(acc[0], acc[4]);
    float2 fS = __half22float2(acc[0]);
    float  S  = fS.x + fS.y;

    // ---- stage 2 via half-warp shuffles (S for group ic lives in this half-warp) ----
    {
        const int l = tid & 15, ic = tid >> 4;   // thread (ic,l); own S is S[ic][l]
        float a = 0.0f;
        #pragma unroll
        for (int j = 0; j < TI; j++) {
            float sj = __shfl_sync(0xffffffffu, S, j, 16);   // S[ic][j]
            a += ((nmJ[j] >> l) & 1u) ? sj : 0.0f;
        }
        a = ((pmI[ic] >> l) & 1u) ? a : 0.0f;
        A2[l * 17 + ic] = a;
    }
    __syncthreads();

    if (tid < NL) {
        float s = 0.0f;
        #pragma unroll
        for (int c = 0; c < 16; c++) s += A2[tid * 17 + c];
        // deterministic fixed-point accumulation (A_l >= 0 always)
        atomicAdd(&g_acc[tid], (unsigned long long)__float2ll_rn(s * FPSCALE));
        __threadfence();            // publishes g_acc (and tid==0's g_inv write)
    }
    __syncthreads();

    if (tid == 0) {
        unsigned t = atomicAdd(&g_cnt, 1u);
        is_last = (t == NBLK - 1);
    }
    __syncthreads();

    // ---- last block: tiny tail ---------------------------------------------------------
    if (is_last) {
        __threadfence();
        if (tid < NL) {
            long long v = (long long)g_acc[tid];
            wfin[tid] = (float)v * FPSCALE_I * g_inv[tid];
            g_acc[tid] = 0ULL;      // reset for next graph replay
        }
        __syncthreads();
        if (tid == 0) {
            float loss = 0.0f;
            #pragma unroll
            for (int l2 = 0; l2 < NL; l2++) loss += wfin[l2];
            out[0] = loss;
            g_cnt  = 0;             // reset for next graph replay
        }
        for (int i = tid + 1; i < n_out; i += 256) out[i] = 0.0f;
    }
}

extern "C" void kernel_launch(void* const* d_in, const int* in_sizes, int n_in,
                              void* d_out, int out_size) {
    const int*   yt  = (const int*)d_in[0];    // y_true int32 [512*16]
    const float* yp  = (const float*)d_in[1];  // y_pred fp32  [512*16]
    float*       out = (float*)d_out;

    k_all<<<NBLK, 256>>>(yt, yp, out, out_size);
}

// round 17
// speedup vs baseline: 1.1800x; 1.0175x over previous
#include <cuda_runtime.h>
#include <cuda_fp16.h>

// B=512 rows, L=16 labels, N=8192 values. Single kernel, 1024 blocks.
// loss = sum_l inv[l] * A_l,  inv[l] = 1/((np*nn)^2 * 256)
// A_l  = sum_{i pos, j neg} S[i,j],  S[i,j] = sum_{c,d} relu(1 - x[i,c] + x[j,d])
// Hot loop: HFMA2.RELU + HADD2 (1 fma-pipe instr per element pair).
// g_inv distributed over blocks 0..15 (one label each; covered by staging sync).
// Epilogue: warps 1..7 exit after writing A2; warp 0 alone reduces, does the
// fixed-point atomics + ticket, and (if last) the warp-local tail. Zero
// trailing barriers. Deterministic throughout.

#define NROW 512
#define NL   16
#define TI   16
#define GB   32
#define NBLK 1024
#define FPSCALE    67108864.0f   // 2^26
#define FPSCALE_I  (1.0f / 67108864.0f)

__device__ float              g_inv[NL];
__device__ unsigned long long g_acc[NL];     // zero-initialized at load
__device__ unsigned int       g_cnt = 0;

__global__ void __launch_bounds__(256, 6) k_all(const int* __restrict__ yt,
                                                const float* __restrict__ yp,
                                                float* __restrict__ out, int n_out) {
    __shared__ __align__(16) __half  xih[TI * TI];   // (1-x) halves [i-row][c]
    __shared__ __align__(16) __half2 xjh2[TI * TI];  // splatted j halves [j-row][d]
    __shared__ float    Ss[256];                     // per-thread S
    __shared__ float    A2[NL * 17];                 // stage-2 partials [l][ic]
    __shared__ unsigned pmI[TI], nmJ[TI];
    __shared__ int      wcnt[8];                     // per-warp popcounts (blocks<16)

    const int b   = blockIdx.x;
    const int bi  = b & (GB - 1);
    const int bj  = b >> 5;
    const int tid = threadIdx.x;

    // ---- stage tiles (convert to fp16 once here) -----------------------------------
    {
        int r = tid >> 4, c = tid & 15;
        xih[r * TI + c]  = __float2half(1.0f - yp[bi * 256 + tid]);
        xjh2[r * TI + c] = __float2half2_rn(yp[bj * 256 + r * TI + c]);
    }

    // ---- row masks: 16 i-rows + 16 j-rows --------------------------------------------
    if (tid < 2 * TI) {
        int row = (tid < TI) ? (bi * TI + tid) : (bj * TI + (tid - TI));
        unsigned m = 0;
        const int4* y4 = (const int4*)(yt + row * NL);
        #pragma unroll
        for (int q = 0; q < 4; q++) {
            int4 v = y4[q];
            if (v.x) m |= 1u << (4 * q + 0);
            if (v.y) m |= 1u << (4 * q + 1);
            if (v.z) m |= 1u << (4 * q + 2);
            if (v.w) m |= 1u << (4 * q + 3);
        }
        if (tid < TI) pmI[tid] = m;
        else          nmJ[tid - TI] = (~m) & 0xFFFFu;
    }

    // ---- distributed g_inv: block b (b<16) counts label b (no extra barriers) --------
    if (b < NL) {
        int v0 = yt[tid * NL + b]         ? 1 : 0;   // rows 0..255
        int v1 = yt[(tid + 256) * NL + b] ? 1 : 0;   // rows 256..511
        unsigned b0 = __ballot_sync(0xffffffffu, v0);
        unsigned b1 = __ballot_sync(0xffffffffu, v1);
        if ((tid & 31) == 0) wcnt[tid >> 5] = __popc(b0) + __popc(b1);
    }
    __syncthreads();                     // covers staging, masks, and wcnt

    if (b < NL && tid == 0) {
        int np = ((wcnt[0] + wcnt[1]) + (wcnt[2] + wcnt[3]))
               + ((wcnt[4] + wcnt[5]) + (wcnt[6] + wcnt[7]));
        int nn = NROW - np;
        float d = (float)np * (float)nn;             // <= 2^18, exact in fp32
        g_inv[b] = (np > 0 && nn > 0) ? 1.0f / (d * d * 256.0f) : 0.0f;
        // ordered before this thread's ticket by the epilogue __threadfence
    }

    // ---- hot loop ----------------------------------------------------------------------
    const int il = tid >> 4;
    const int jl = tid & 15;

    // ah: 8 half2 of (1-x), 2x LDS.128 (half-warp broadcast, conflict-free)
    __half2 ah[8];
    {
        uint4 a0 = *(const uint4*)(xih + il * TI);
        uint4 a1 = *(const uint4*)(xih + il * TI + 8);
        unsigned aw[8] = {a0.x, a0.y, a0.z, a0.w, a1.x, a1.y, a1.z, a1.w};
        #pragma unroll
        for (int k = 0; k < 8; k++) ah[k] = *reinterpret_cast<__half2*>(&aw[k]);
    }

    const __half2 one2 = __float2half2_rn(1.0f);
    const __half2 hz   = __float2half2_rn(0.0f);
    __half2 acc[8];
    #pragma unroll
    for (int k = 0; k < 8; k++) acc[k] = hz;

    const uint4* qp = (const uint4*)&xjh2[jl * TI];   // 16 splatted half2
    #pragma unroll
    for (int dc = 0; dc < 4; dc++) {
        uint4 qv = qp[dc];
        unsigned qw[4] = {qv.x, qv.y, qv.z, qv.w};
        #pragma unroll
        for (int di = 0; di < 4; di++) {
            __half2 xq = *reinterpret_cast<__half2*>(&qw[di]);
            #pragma unroll
            for (int k = 0; k < 8; k++) {
                __half2 r = __hfma2_relu(ah[k], one2, xq);   // relu(ah + xq)
                acc[k] = __hadd2(acc[k], r);
            }
        }
    }

    // tree-reduce the 8 half2 accumulators (values ~330 << 65504: safe)
    acc[0] = __hadd2(acc[0], acc[1]);
    acc[2] = __hadd2(acc[2], acc[3]);
    acc[4] = __hadd2(acc[4], acc[5]);
    acc[6] = __hadd2(acc[6], acc[7]);
    acc[0] = __hadd2(acc[0], acc[2]);
    acc[4] = __hadd2(acc[4], acc[6]);
    acc[0] = __hadd2(acc[0], acc[4]);
    float2 fS = __half22float2(acc[0]);

    // ---- epilogue stage 1: store S once ---------------------------------------------
    Ss[tid] = fS.x + fS.y;
    __syncthreads();

    // ---- stage 2: reconstruct label sums from masks (LDS broadcast, conflict-free) ---
    {
        const int l = tid & 15, ic = tid >> 4;
        float a = 0.0f;
        if ((pmI[ic] >> l) & 1u) {
            #pragma unroll
            for (int j = 0; j < TI; j++)
                a += ((nmJ[j] >> l) & 1u) ? Ss[ic * TI + j] : 0.0f;
        }
        A2[l * 17 + ic] = a;
    }
    __syncthreads();

    // ---- warps 1..7 exit here; warp 0 finishes the block ------------------------------
    if (tid >= 32) return;

    const unsigned FULL = 0xffffffffu;
    if (tid < NL) {
        float s = 0.0f;
        #pragma unroll
        for (int c = 0; c < 16; c++) s += A2[tid * 17 + c];
        // deterministic fixed-point accumulation (A_l >= 0 always)
        atomicAdd(&g_acc[tid], (unsigned long long)__float2ll_rn(s * FPSCALE));
    }
    __threadfence();                 // publishes g_acc adds (and tid0's g_inv write)

    unsigned last = 0;
    if (tid == 0) {
        unsigned t = atomicAdd(&g_cnt, 1u);
        last = (t == NBLK - 1) ? 1u : 0u;
    }
    last = __shfl_sync(FULL, last, 0);

    // ---- last block: warp-local tail ---------------------------------------------------
    if (last) {
        __threadfence();
        float w = 0.0f;
        if (tid < NL) {
            long long v = (long long)g_acc[tid];
            w = (float)v * FPSCALE_I * g_inv[tid];
            g_acc[tid] = 0ULL;       // reset for next graph replay
        }
        // warp tree-reduce the 16 label values (fixed order: deterministic)
        #pragma unroll
        for (int o = 8; o > 0; o >>= 1)
            w += __shfl_down_sync(FULL, w, o, 32);
        if (tid == 0) {
            out[0] = w;
            g_cnt  = 0;              // reset for next graph replay
        }
        for (int i = tid + 1; i < n_out; i += 32) out[i] = 0.0f;
    }
}

extern "C" void kernel_launch(void* const* d_in, const int* in_sizes, int n_in,
                              void* d_out, int out_size) {
    const int*   yt  = (const int*)d_in[0];    // y_true int32 [512*16]
    const float* yp  = (const float*)d_in[1];  // y_pred fp32  [512*16]
    float*       out = (float*)d_out;

    k_all<<<NBLK, 256>>>(yt, yp, out, out_size);
}